// round 16
// baseline (speedup 1.0000x reference)
#include <cuda_runtime.h>
#include <cuda_fp16.h>
#include <cuda_bf16.h>
#include <cstdint>

#define BATCH      32
#define W_DIM      512
#define CHANNELS   1024
#define GRID_HW    64
#define HW         (GRID_HW * GRID_HW)      // 4096
#define TWO_PI     6.28318530717958647692f
#define GAIN       0.044194173824159216f    // 1/sqrt(512)
#define WSCALE     0.03125f                 // 1/sqrt(1024)

// ---------------- scratch (device globals; no runtime alloc) -----------------
// trig tables in fragment-grouped layout:
// idx = (b*64+p)*1024 + kt*16 + tg*4 + e,  e indexes c = {2tg,2tg+1,2tg+8,2tg+9}+16kt
__device__ __half g_SAP[BATCH * GRID_HW * CHANNELS];
__device__ __half g_CAP[BATCH * GRID_HW * CHANNELS];
__device__ __half g_SBP[BATCH * GRID_HW * CHANNELS];
__device__ __half g_CBP[BATCH * GRID_HW * CHANNELS];

// A packed in mma fragment layout: PW[mt(64)][kt(64)][lane(32)][8 halves=a0..a3]
__device__ __half g_PW[64 * 64 * 256];
// B packed: PB[b(32)][np(256)][kt(64)][lane(32)][8 halves]
__device__ __half g_PB[(size_t)BATCH * 256 * 64 * 256];

// ---------------- mma helper -------------------------------------------------
__device__ __forceinline__ void mma16816(float* d, const uint32_t* a,
                                         const uint32_t* b) {
    asm volatile(
        "mma.sync.aligned.m16n8k16.row.col.f32.f16.f16.f32 "
        "{%0,%1,%2,%3}, {%4,%5,%6,%7}, {%8,%9}, {%0,%1,%2,%3};"
        : "+f"(d[0]), "+f"(d[1]), "+f"(d[2]), "+f"(d[3])
        : "r"(a[0]), "r"(a[1]), "r"(a[2]), "r"(a[3]), "r"(b[0]), "r"(b[1]));
}

// ---------------- stage 1b: weight -> packed A fragments ---------------------
__global__ void wconv_kernel(const float* __restrict__ weight) {
    int idx = blockIdx.x * blockDim.x + threadIdx.x;
    for (int i = idx; i < CHANNELS * CHANNELS; i += gridDim.x * blockDim.x) {
        int o = i >> 10, c = i & 1023;
        int mt = o >> 4, r = o & 15;
        int g = r & 7, rowhi = r >> 3;
        int kt = c >> 4, rem = c & 15;
        int tg = (rem & 7) >> 1;
        int khi = rem >> 3;
        int e = rem & 1;
        int lane = g * 4 + tg;
        int reg = khi * 2 + rowhi;
        size_t off = (((size_t)mt * 64 + kt) * 32 + lane) * 8 + reg * 2 + e;
        g_PW[off] = __float2half(weight[i] * WSCALE);
    }
}

// ---------------- stage 2: params + trig tables fused ------------------------
// Per-block redundant affine compute (2k FMA), then fragment-grouped tables.
__global__ void __launch_bounds__(256)
tables_kernel(const float* __restrict__ w,
              const float* __restrict__ affine_w,
              const float* __restrict__ affine_b,
              const float* __restrict__ freqs,
              const float* __restrict__ phases) {
    __shared__ float t[4];
    __shared__ float sC, sS, sTX, sTY;

    int p = blockIdx.x, b = blockIdx.y;
    int tid = threadIdx.x;
    int j = tid >> 5, lane = tid & 31;

    if (j < 4) {
        float acc = 0.f;
        const float* wr = w + b * W_DIM;
        const float* ar = affine_w + j * W_DIM;
        for (int k = lane; k < W_DIM; k += 32) acc += wr[k] * ar[k];
        #pragma unroll
        for (int s = 16; s > 0; s >>= 1)
            acc += __shfl_down_sync(0xFFFFFFFF, acc, s);
        if (lane == 0) t[j] = acc * GAIN + affine_b[j];
    }
    __syncthreads();
    if (tid == 0) {
        float t0 = t[0], t1 = t[1], t2 = t[2], t3 = t[3];
        float inv = rsqrtf(t0 * t0 + t1 * t1);
        float c = t0 * inv, s = t1 * inv, tx = t2 * inv, ty = t3 * inv;
        sC = c; sS = s;
        sTX = -c * tx + s * ty;
        sTY = -s * tx - c * ty;
    }
    __syncthreads();

    float C = sC, S = sS, TX = sTX, TY = sTY;
    float g = ((2 * p + 1) * (1.0f / GRID_HW) - 1.0f) * 0.5f;
    size_t base = ((size_t)(b * GRID_HW + p)) << 10;
    for (int c = tid; c < CHANNELS; c += 256) {
        float f0 = freqs[c * 2], f1 = freqs[c * 2 + 1];
        float frx = f0 * C + f1 * S;
        float fry = -f0 * S + f1 * C;
        float ph  = phases[c] + f0 * TX + f1 * TY;
        float sa, ca, sb, cb;
        sincosf(TWO_PI * g * frx, &sa, &ca);
        sincosf(TWO_PI * (g * fry + ph), &sb, &cb);
        int kt = c >> 4, rem = c & 15;
        int tg = (rem & 7) >> 1;
        int e = (rem & 1) + ((rem >> 3) << 1);
        size_t off = base + kt * 16 + tg * 4 + e;
        g_SAP[off] = __float2half(sa);
        g_CAP[off] = __float2half(ca);
        g_SBP[off] = __float2half(sb);
        g_CBP[off] = __float2half(cb);
    }
}

// ---------------- stage 3: packed B, h-blocked (8 h per block) ---------------
__global__ void __launch_bounds__(256)
features_kernel() {
    __shared__ __half sSB[8 * 1024], sCB[8 * 1024];
    int hg = blockIdx.x;   // 0..7
    int b  = blockIdx.y;
    int tid = threadIdx.x;

    for (int i = tid; i < 1024; i += 256) {
        int r = i >> 7, q = i & 127;
        size_t src = (((size_t)(b * GRID_HW + hg * 8 + r)) << 10) + q * 8;
        *(uint4*)&sSB[r * 1024 + q * 8] = *(const uint4*)&g_SBP[src];
        *(uint4*)&sCB[r * 1024 + q * 8] = *(const uint4*)&g_CBP[src];
    }
    __syncthreads();

    int wp = tid >> 5, lane = tid & 31;
    int g = lane >> 2, tg = lane & 3;

    for (int kt = wp; kt < 64; kt += 8) {
        #pragma unroll
        for (int npl = 0; npl < 4; npl++) {
            int w0 = npl * 16 + g, w1 = w0 + 8;
            size_t o0 = (((size_t)(b * GRID_HW + w0)) << 10) + kt * 16 + tg * 4;
            size_t o1 = (((size_t)(b * GRID_HW + w1)) << 10) + kt * 16 + tg * 4;
            uint2 sa0 = *(const uint2*)&g_SAP[o0];
            uint2 ca0 = *(const uint2*)&g_CAP[o0];
            uint2 sa1 = *(const uint2*)&g_SAP[o1];
            uint2 ca1 = *(const uint2*)&g_CAP[o1];

            #pragma unroll
            for (int hr = 0; hr < 8; hr++) {
                int sidx = hr * 1024 + kt * 16 + tg * 4;
                uint2 sbv = *(const uint2*)&sSB[sidx];
                uint2 cbv = *(const uint2*)&sCB[sidx];
                __half2 sb01 = *(__half2*)&sbv.x, sb23 = *(__half2*)&sbv.y;
                __half2 cb01 = *(__half2*)&cbv.x, cb23 = *(__half2*)&cbv.y;

                uint4 outv;
                ((__half2*)&outv)[0] = __hfma2(*(__half2*)&sa0.x, cb01,
                                       __hmul2(*(__half2*)&ca0.x, sb01));
                ((__half2*)&outv)[1] = __hfma2(*(__half2*)&sa0.y, cb23,
                                       __hmul2(*(__half2*)&ca0.y, sb23));
                ((__half2*)&outv)[2] = __hfma2(*(__half2*)&sa1.x, cb01,
                                       __hmul2(*(__half2*)&ca1.x, sb01));
                ((__half2*)&outv)[3] = __hfma2(*(__half2*)&sa1.y, cb23,
                                       __hmul2(*(__half2*)&ca1.y, sb23));

                int h = hg * 8 + hr;
                size_t dst = ((((size_t)b * 256 + h * 4 + npl) * 64 + kt) * 32
                              + lane) * 8;
                *(uint4*)&g_PB[dst] = outv;
            }
        }
    }
}

// ---------------- stage 4: smem-free fragment-direct GEMM --------------------
// CTA 256(o) x 128(px); 8 warps 4m x 2n, 64x64 each. No smem, no barriers.
// 3-deep register pipeline; loads interleaved INSIDE each MMA step (half-step
// granularity) to smooth LSU bursts / cut peak outstanding misses.
#define LDG_NC4(d, p_)                                                     \
    asm volatile("ld.global.nc.v4.u32 {%0,%1,%2,%3}, [%4];"                \
                 : "=r"((d).x), "=r"((d).y), "=r"((d).z), "=r"((d).w)      \
                 : "l"(p_))

#define LD_A01(u, kt_) do {                                                \
    uint32_t ko = (uint32_t)(kt_) * 512;                                   \
    LDG_NC4(af[u][0], paB + 0 * 32768 + ko);                               \
    LDG_NC4(af[u][1], paB + 1 * 32768 + ko);                               \
} while (0)

#define LD_A23(u, kt_) do {                                                \
    uint32_t ko = (uint32_t)(kt_) * 512;                                   \
    LDG_NC4(af[u][2], paB + 2 * 32768 + ko);                               \
    LDG_NC4(af[u][3], paB + 3 * 32768 + ko);                               \
} while (0)

#define LD_B4(u, kt_) do {                                                 \
    uint32_t ko = (uint32_t)(kt_) * 512;                                   \
    LDG_NC4(bf[u][0], pbB + 0 * 32768 + ko);                               \
    LDG_NC4(bf[u][1], pbB + 1 * 32768 + ko);                               \
    LDG_NC4(bf[u][2], pbB + 2 * 32768 + ko);                               \
    LDG_NC4(bf[u][3], pbB + 3 * 32768 + ko);                               \
} while (0)

#define PF_B(kt_) do {                                                     \
    uint32_t ko = (uint32_t)(kt_) * 512;                                   \
    asm volatile("prefetch.global.L2 [%0];" :: "l"(pbB + 0 * 32768 + ko)); \
    asm volatile("prefetch.global.L2 [%0];" :: "l"(pbB + 1 * 32768 + ko)); \
    asm volatile("prefetch.global.L2 [%0];" :: "l"(pbB + 2 * 32768 + ko)); \
    asm volatile("prefetch.global.L2 [%0];" :: "l"(pbB + 3 * 32768 + ko)); \
} while (0)

#define MMA_H1(u) do {                                                     \
    _Pragma("unroll")                                                      \
    for (int i = 0; i < 2; i++) {                                          \
        const uint32_t* a = (const uint32_t*)&af[u][i];                    \
        _Pragma("unroll")                                                  \
        for (int j2 = 0; j2 < 4; j2++) {                                   \
            const uint32_t* bp = (const uint32_t*)&bf[u][j2];              \
            mma16816(acc[i][2 * j2],     a, bp);                           \
            mma16816(acc[i][2 * j2 + 1], a, bp + 2);                       \
        }                                                                  \
    }                                                                      \
} while (0)

#define MMA_H2(u) do {                                                     \
    _Pragma("unroll")                                                      \
    for (int i = 2; i < 4; i++) {                                          \
        const uint32_t* a = (const uint32_t*)&af[u][i];                    \
        _Pragma("unroll")                                                  \
        for (int j2 = 0; j2 < 4; j2++) {                                   \
            const uint32_t* bp = (const uint32_t*)&bf[u][j2];              \
            mma16816(acc[i][2 * j2],     a, bp);                           \
            mma16816(acc[i][2 * j2 + 1], a, bp + 2);                       \
        }                                                                  \
    }                                                                      \
} while (0)

__global__ void __launch_bounds__(256, 1)
gemm_mma(float* __restrict__ out) {
    int tid = threadIdx.x;
    int ot = blockIdx.x;   // 4   (x-major: ot-CTAs sharing a PB slice co-run)
    int pt = blockIdx.y;   // 32
    int b  = blockIdx.z;   // 32

    int wid = tid >> 5, lane = tid & 31;
    int wm = wid >> 1;             // 0..3
    int wn = wid & 1;              // 0..1
    int mt0 = ot * 16 + wm * 4;
    int np0 = pt * 8 + wn * 4;

    const char* paB = (const char*)(g_PW + ((size_t)mt0 * 64 * 256 + lane * 8));
    const char* pbB = (const char*)(g_PB + (((size_t)b * 256 + np0) * 64 * 256
                                            + lane * 8));

    uint4 af[3][4], bf[3][4];
    float acc[4][8][4];
    #pragma unroll
    for (int i = 0; i < 4; i++)
        #pragma unroll
        for (int j = 0; j < 8; j++)
            #pragma unroll
            for (int q = 0; q < 4; q++) acc[i][j][q] = 0.f;

    PF_B(3); PF_B(4); PF_B(5); PF_B(6); PF_B(7); PF_B(8);
    LD_A01(0, 0); LD_A23(0, 0); LD_B4(0, 0);
    LD_A01(1, 1); LD_A23(1, 1); LD_B4(1, 1);
    LD_A01(2, 2); LD_A23(2, 2); LD_B4(2, 2);

    // loop covers kt = 0..62 in steps of 3; buffer u holds kt+u at loop head
    #pragma unroll 1
    for (int kt = 0; kt < 63; kt += 3) {
        int kn0 = kt + 3;                               // <= 63 always
        int kn1 = kt + 4; if (kn1 > 63) kn1 = 63;
        int kn2 = kt + 5; if (kn2 > 63) kn2 = 63;
        int kp0 = kt + 9;  if (kp0 > 63) kp0 = 63;
        int kp1 = kt + 10; if (kp1 > 63) kp1 = 63;
        int kp2 = kt + 11; if (kp2 > 63) kp2 = 63;

        PF_B(kp0);
        MMA_H1(0); LD_A01(0, kn0);
        MMA_H2(0); LD_A23(0, kn0); LD_B4(0, kn0);

        PF_B(kp1);
        MMA_H1(1); LD_A01(1, kn1);
        MMA_H2(1); LD_A23(1, kn1); LD_B4(1, kn1);

        PF_B(kp2);
        MMA_H1(2); LD_A01(2, kn2);
        MMA_H2(2); LD_A23(2, kn2); LD_B4(2, kn2);
    }
    // tail: kt = 63 lives in buffer 0 (63 % 3 == 0)
    MMA_H1(0); MMA_H2(0);

    // ---- epilogue: c0,c1 -> (row, col 2tg,2tg+1); c2,c3 -> row+8 ------------
    int g = lane >> 2, tg = lane & 3;
    #pragma unroll
    for (int i = 0; i < 4; i++) {
        int o = ot * 256 + wm * 64 + i * 16 + g;
        float* p = out + ((size_t)(b * CHANNELS + o)) * HW
                       + (size_t)pt * 128 + wn * 64 + 2 * tg;
        #pragma unroll
        for (int jn = 0; jn < 8; jn++) {
            *(float2*)(p + jn * 8)          = make_float2(acc[i][jn][0], acc[i][jn][1]);
            *(float2*)(p + jn * 8 + 8 * HW) = make_float2(acc[i][jn][2], acc[i][jn][3]);
        }
    }
}

// ---------------- launch ------------------------------------------------------
extern "C" void kernel_launch(void* const* d_in, const int* in_sizes, int n_in,
                              void* d_out, int out_size) {
    const float* w        = (const float*)d_in[0];
    const float* affine_w = (const float*)d_in[1];
    const float* affine_b = (const float*)d_in[2];
    const float* freqs    = (const float*)d_in[3];
    const float* phases   = (const float*)d_in[4];
    const float* weight   = (const float*)d_in[5];
    float* out = (float*)d_out;

    wconv_kernel<<<512, 256>>>(weight);
    tables_kernel<<<dim3(GRID_HW, BATCH), 256>>>(w, affine_w, affine_b,
                                                 freqs, phases);
    features_kernel<<<dim3(GRID_HW / 8, BATCH), 256>>>();
    gemm_mma<<<dim3(4, 32, BATCH), 256>>>(out);
}

// round 17
// speedup vs baseline: 1.1975x; 1.1975x over previous
#include <cuda_runtime.h>
#include <cuda_fp16.h>
#include <cuda_bf16.h>
#include <cstdint>

#define BATCH      32
#define W_DIM      512
#define CHANNELS   1024
#define GRID_HW    64
#define HW         (GRID_HW * GRID_HW)      // 4096
#define TWO_PI     6.28318530717958647692f
#define GAIN       0.044194173824159216f    // 1/sqrt(512)
#define WSCALE     0.03125f                 // 1/sqrt(1024)

// ---------------- scratch (device globals; no runtime alloc) -----------------
// trig tables in fragment-grouped layout:
// idx = (b*64+p)*1024 + kt*16 + tg*4 + e,  e indexes c = {2tg,2tg+1,2tg+8,2tg+9}+16kt
__device__ __half g_SAP[BATCH * GRID_HW * CHANNELS];
__device__ __half g_CAP[BATCH * GRID_HW * CHANNELS];
__device__ __half g_SBP[BATCH * GRID_HW * CHANNELS];
__device__ __half g_CBP[BATCH * GRID_HW * CHANNELS];

// A packed in mma fragment layout: PW[mt(64)][kt(64)][lane(32)][8 halves=a0..a3]
__device__ __half g_PW[64 * 64 * 256];
// B packed: PB[b(32)][np(256)][kt(64)][lane(32)][8 halves]
__device__ __half g_PB[(size_t)BATCH * 256 * 64 * 256];

// ---------------- mma helper -------------------------------------------------
__device__ __forceinline__ void mma16816(float* d, const uint32_t* a,
                                         const uint32_t* b) {
    asm volatile(
        "mma.sync.aligned.m16n8k16.row.col.f32.f16.f16.f32 "
        "{%0,%1,%2,%3}, {%4,%5,%6,%7}, {%8,%9}, {%0,%1,%2,%3};"
        : "+f"(d[0]), "+f"(d[1]), "+f"(d[2]), "+f"(d[3])
        : "r"(a[0]), "r"(a[1]), "r"(a[2]), "r"(a[3]), "r"(b[0]), "r"(b[1]));
}

// ---------------- stage 1b: weight -> packed A fragments ---------------------
__global__ void wconv_kernel(const float* __restrict__ weight) {
    int idx = blockIdx.x * blockDim.x + threadIdx.x;
    for (int i = idx; i < CHANNELS * CHANNELS; i += gridDim.x * blockDim.x) {
        int o = i >> 10, c = i & 1023;
        int mt = o >> 4, r = o & 15;
        int g = r & 7, rowhi = r >> 3;
        int kt = c >> 4, rem = c & 15;
        int tg = (rem & 7) >> 1;
        int khi = rem >> 3;
        int e = rem & 1;
        int lane = g * 4 + tg;
        int reg = khi * 2 + rowhi;
        size_t off = (((size_t)mt * 64 + kt) * 32 + lane) * 8 + reg * 2 + e;
        g_PW[off] = __float2half(weight[i] * WSCALE);
    }
}

// ---------------- stage 2: params + trig tables fused ------------------------
__global__ void __launch_bounds__(256)
tables_kernel(const float* __restrict__ w,
              const float* __restrict__ affine_w,
              const float* __restrict__ affine_b,
              const float* __restrict__ freqs,
              const float* __restrict__ phases) {
    __shared__ float t[4];
    __shared__ float sC, sS, sTX, sTY;

    int p = blockIdx.x, b = blockIdx.y;
    int tid = threadIdx.x;
    int j = tid >> 5, lane = tid & 31;

    if (j < 4) {
        float acc = 0.f;
        const float* wr = w + b * W_DIM;
        const float* ar = affine_w + j * W_DIM;
        for (int k = lane; k < W_DIM; k += 32) acc += wr[k] * ar[k];
        #pragma unroll
        for (int s = 16; s > 0; s >>= 1)
            acc += __shfl_down_sync(0xFFFFFFFF, acc, s);
        if (lane == 0) t[j] = acc * GAIN + affine_b[j];
    }
    __syncthreads();
    if (tid == 0) {
        float t0 = t[0], t1 = t[1], t2 = t[2], t3 = t[3];
        float inv = rsqrtf(t0 * t0 + t1 * t1);
        float c = t0 * inv, s = t1 * inv, tx = t2 * inv, ty = t3 * inv;
        sC = c; sS = s;
        sTX = -c * tx + s * ty;
        sTY = -s * tx - c * ty;
    }
    __syncthreads();

    float C = sC, S = sS, TX = sTX, TY = sTY;
    float g = ((2 * p + 1) * (1.0f / GRID_HW) - 1.0f) * 0.5f;
    size_t base = ((size_t)(b * GRID_HW + p)) << 10;
    for (int c = tid; c < CHANNELS; c += 256) {
        float f0 = freqs[c * 2], f1 = freqs[c * 2 + 1];
        float frx = f0 * C + f1 * S;
        float fry = -f0 * S + f1 * C;
        float ph  = phases[c] + f0 * TX + f1 * TY;
        float sa, ca, sb, cb;
        sincosf(TWO_PI * g * frx, &sa, &ca);
        sincosf(TWO_PI * (g * fry + ph), &sb, &cb);
        int kt = c >> 4, rem = c & 15;
        int tg = (rem & 7) >> 1;
        int e = (rem & 1) + ((rem >> 3) << 1);
        size_t off = base + kt * 16 + tg * 4 + e;
        g_SAP[off] = __float2half(sa);
        g_CAP[off] = __float2half(ca);
        g_SBP[off] = __float2half(sb);
        g_CBP[off] = __float2half(cb);
    }
}

// ---------------- stage 3: packed B, h-blocked (8 h per block) ---------------
__global__ void __launch_bounds__(256)
features_kernel() {
    __shared__ __half sSB[8 * 1024], sCB[8 * 1024];
    int hg = blockIdx.x;   // 0..7
    int b  = blockIdx.y;
    int tid = threadIdx.x;

    for (int i = tid; i < 1024; i += 256) {
        int r = i >> 7, q = i & 127;
        size_t src = (((size_t)(b * GRID_HW + hg * 8 + r)) << 10) + q * 8;
        *(uint4*)&sSB[r * 1024 + q * 8] = *(const uint4*)&g_SBP[src];
        *(uint4*)&sCB[r * 1024 + q * 8] = *(const uint4*)&g_CBP[src];
    }
    __syncthreads();

    int wp = tid >> 5, lane = tid & 31;
    int g = lane >> 2, tg = lane & 3;

    for (int kt = wp; kt < 64; kt += 8) {
        #pragma unroll
        for (int npl = 0; npl < 4; npl++) {
            int w0 = npl * 16 + g, w1 = w0 + 8;
            size_t o0 = (((size_t)(b * GRID_HW + w0)) << 10) + kt * 16 + tg * 4;
            size_t o1 = (((size_t)(b * GRID_HW + w1)) << 10) + kt * 16 + tg * 4;
            uint2 sa0 = *(const uint2*)&g_SAP[o0];
            uint2 ca0 = *(const uint2*)&g_CAP[o0];
            uint2 sa1 = *(const uint2*)&g_SAP[o1];
            uint2 ca1 = *(const uint2*)&g_CAP[o1];

            #pragma unroll
            for (int hr = 0; hr < 8; hr++) {
                int sidx = hr * 1024 + kt * 16 + tg * 4;
                uint2 sbv = *(const uint2*)&sSB[sidx];
                uint2 cbv = *(const uint2*)&sCB[sidx];
                __half2 sb01 = *(__half2*)&sbv.x, sb23 = *(__half2*)&sbv.y;
                __half2 cb01 = *(__half2*)&cbv.x, cb23 = *(__half2*)&cbv.y;

                uint4 outv;
                ((__half2*)&outv)[0] = __hfma2(*(__half2*)&sa0.x, cb01,
                                       __hmul2(*(__half2*)&ca0.x, sb01));
                ((__half2*)&outv)[1] = __hfma2(*(__half2*)&sa0.y, cb23,
                                       __hmul2(*(__half2*)&ca0.y, sb23));
                ((__half2*)&outv)[2] = __hfma2(*(__half2*)&sa1.x, cb01,
                                       __hmul2(*(__half2*)&ca1.x, sb01));
                ((__half2*)&outv)[3] = __hfma2(*(__half2*)&sa1.y, cb23,
                                       __hmul2(*(__half2*)&ca1.y, sb23));

                int h = hg * 8 + hr;
                size_t dst = ((((size_t)b * 256 + h * 4 + npl) * 64 + kt) * 32
                              + lane) * 8;
                *(uint4*)&g_PB[dst] = outv;
            }
        }
    }
}

// ---------------- stage 4: smem-free fragment-direct GEMM --------------------
// CTA 128(o) x 128(px); 8 warps 4m x 2n of 32x64. 2 CTAs/SM (16 warps/SM).
// Depth-2 register pipeline + L2 prefetch; no smem, no barriers.
#define LDG_NC4(d, p_)                                                     \
    asm volatile("ld.global.nc.v4.u32 {%0,%1,%2,%3}, [%4];"                \
                 : "=r"((d).x), "=r"((d).y), "=r"((d).z), "=r"((d).w)      \
                 : "l"(p_))

#define LD_FRAGS(u, kt_) do {                                              \
    uint32_t ko = (uint32_t)(kt_) * 512;                                   \
    LDG_NC4(af[u][0], paB + 0 * 32768 + ko);                               \
    LDG_NC4(af[u][1], paB + 1 * 32768 + ko);                               \
    LDG_NC4(bf[u][0], pbB + 0 * 32768 + ko);                               \
    LDG_NC4(bf[u][1], pbB + 1 * 32768 + ko);                               \
    LDG_NC4(bf[u][2], pbB + 2 * 32768 + ko);                               \
    LDG_NC4(bf[u][3], pbB + 3 * 32768 + ko);                               \
} while (0)

#define PF_B(kt_) do {                                                     \
    uint32_t ko = (uint32_t)(kt_) * 512;                                   \
    asm volatile("prefetch.global.L2 [%0];" :: "l"(pbB + 0 * 32768 + ko)); \
    asm volatile("prefetch.global.L2 [%0];" :: "l"(pbB + 1 * 32768 + ko)); \
    asm volatile("prefetch.global.L2 [%0];" :: "l"(pbB + 2 * 32768 + ko)); \
    asm volatile("prefetch.global.L2 [%0];" :: "l"(pbB + 3 * 32768 + ko)); \
} while (0)

#define MMA_STEP(u) do {                                                   \
    _Pragma("unroll")                                                      \
    for (int i = 0; i < 2; i++) {                                          \
        const uint32_t* a = (const uint32_t*)&af[u][i];                    \
        _Pragma("unroll")                                                  \
        for (int j2 = 0; j2 < 4; j2++) {                                   \
            const uint32_t* bp = (const uint32_t*)&bf[u][j2];              \
            mma16816(acc[i][2 * j2],     a, bp);                           \
            mma16816(acc[i][2 * j2 + 1], a, bp + 2);                       \
        }                                                                  \
    }                                                                      \
} while (0)

__global__ void __launch_bounds__(256, 2)
gemm_mma(float* __restrict__ out) {
    int tid = threadIdx.x;
    int ot = blockIdx.x;   // 8   (x-major: ot-CTAs sharing a PB slice co-run)
    int pt = blockIdx.y;   // 32
    int b  = blockIdx.z;   // 32

    int wid = tid >> 5, lane = tid & 31;
    int wm = wid >> 1;             // 0..3
    int wn = wid & 1;              // 0..1
    int mt0 = ot * 8 + wm * 2;     // m16 tile base (M=128 per CTA)
    int np0 = pt * 8 + wn * 4;

    const char* paB = (const char*)(g_PW + ((size_t)mt0 * 64 * 256 + lane * 8));
    const char* pbB = (const char*)(g_PB + (((size_t)b * 256 + np0) * 64 * 256
                                            + lane * 8));

    uint4 af[2][2], bf[2][4];
    float acc[2][8][4];
    #pragma unroll
    for (int i = 0; i < 2; i++)
        #pragma unroll
        for (int j = 0; j < 8; j++)
            #pragma unroll
            for (int q = 0; q < 4; q++) acc[i][j][q] = 0.f;

    PF_B(2); PF_B(3); PF_B(4); PF_B(5);
    LD_FRAGS(0, 0);
    LD_FRAGS(1, 1);

    #pragma unroll 1
    for (int kt = 0; kt < 64; kt += 2) {
        { int kp = kt + 6; if (kp > 63) kp = 63; PF_B(kp); }
        MMA_STEP(0);
        { int kn = (kt + 2 < 64) ? kt + 2 : 62; LD_FRAGS(0, kn); }
        { int kp = kt + 7; if (kp > 63) kp = 63; PF_B(kp); }
        MMA_STEP(1);
        { int kn = (kt + 3 < 64) ? kt + 3 : 63; LD_FRAGS(1, kn); }
    }

    // ---- epilogue: c0,c1 -> (row, col 2tg,2tg+1); c2,c3 -> row+8 ------------
    int g = lane >> 2, tg = lane & 3;
    #pragma unroll
    for (int i = 0; i < 2; i++) {
        int o = ot * 128 + wm * 32 + i * 16 + g;
        float* p = out + ((size_t)(b * CHANNELS + o)) * HW
                       + (size_t)pt * 128 + wn * 64 + 2 * tg;
        #pragma unroll
        for (int jn = 0; jn < 8; jn++) {
            *(float2*)(p + jn * 8)          = make_float2(acc[i][jn][0], acc[i][jn][1]);
            *(float2*)(p + jn * 8 + 8 * HW) = make_float2(acc[i][jn][2], acc[i][jn][3]);
        }
    }
}

// ---------------- launch ------------------------------------------------------
extern "C" void kernel_launch(void* const* d_in, const int* in_sizes, int n_in,
                              void* d_out, int out_size) {
    const float* w        = (const float*)d_in[0];
    const float* affine_w = (const float*)d_in[1];
    const float* affine_b = (const float*)d_in[2];
    const float* freqs    = (const float*)d_in[3];
    const float* phases   = (const float*)d_in[4];
    const float* weight   = (const float*)d_in[5];
    float* out = (float*)d_out;

    wconv_kernel<<<512, 256>>>(weight);
    tables_kernel<<<dim3(GRID_HW, BATCH), 256>>>(w, affine_w, affine_b,
                                                 freqs, phases);
    features_kernel<<<dim3(GRID_HW / 8, BATCH), 256>>>();
    gemm_mma<<<dim3(8, 32, BATCH), 256>>>(out);
}